// round 7
// baseline (speedup 1.0000x reference)
#include <cuda_runtime.h>
#include <math.h>

#define Tn   2048
#define Hn   2048
#define NHn  16
#define NKVn 4
#define HDn  128
#define En   8
#define Fn   4096
#define FSn  4096
#define QD   (NHn*HDn)   // 2048
#define KD   (NKVn*HDn)  // 512

// ---------------- scratch (__device__ globals; no allocation allowed) ----------------
__device__ float g_x1[Tn*Hn];
__device__ float g_q[Tn*QD];
__device__ float g_k[Tn*KD];
__device__ float g_v[Tn*KD];
__device__ float g_attn[Tn*QD];
__device__ float g_hidden[Tn*Hn];
__device__ float g_x2[Tn*Hn];
__device__ float g_gbuf[2*Tn*Fn];   // gate proj / then act
__device__ float g_ubuf[2*Tn*Fn];   // up proj
__device__ float g_moe[2*Tn*Hn];    // per-slot expert outputs (scaled)
__device__ float g_sgg[Tn*FSn];     // shared-expert gate / act
__device__ float g_sgu[Tn*FSn];     // shared-expert up
__device__ float g_so[Tn*Hn];       // shared-expert out
__device__ float g_sgate[Tn];
__device__ int   g_te[Tn*2];
__device__ float g_tw[Tn*2];
__device__ int   g_ptok[2*Tn];
__device__ int   g_pslot[2*Tn];
__device__ float g_pw[2*Tn];
__device__ int   g_cnt[En];
__device__ int   g_off[En];

// ---------------- rmsnorm ----------------
__global__ void __launch_bounds__(256) rmsnorm_kernel(
    const float* __restrict__ x, const float* __restrict__ w, float* __restrict__ y)
{
    int t = blockIdx.x, tid = threadIdx.x;
    __shared__ float red[256];
    __shared__ float rs;
    const float* xr = x + (size_t)t*Hn;
    float s = 0.f;
    for (int j = tid; j < Hn; j += 256) { float v = xr[j]; s += v*v; }
    red[tid] = s; __syncthreads();
    for (int o = 128; o > 0; o >>= 1) { if (tid < o) red[tid] += red[tid+o]; __syncthreads(); }
    if (tid == 0) rs = rsqrtf(red[0]/(float)Hn + 1e-6f);
    __syncthreads();
    float* yr = y + (size_t)t*Hn;
    for (int j = tid; j < Hn; j += 256) yr[j] = xr[j]*rs*w[j];
}

// ---------------- generic fp32 GEMM: C = A@B (+Cadd), row-major ----------------
// 128x128 tile, BK=8, 256 threads, 8x8 per-thread register blocking.
// N multiple of 128, K multiple of 8; M guarded.
__global__ void __launch_bounds__(256) gemm_f32(
    const float* __restrict__ A, const float* __restrict__ B,
    const float* __restrict__ Cadd, float* __restrict__ C,
    int M, int N, int K)
{
    __shared__ float As[8][128];
    __shared__ float Bs[8][128];
    const int tid = threadIdx.x;
    const int bm = blockIdx.y * 128, bn = blockIdx.x * 128;
    const int tx = tid & 15, ty = tid >> 4;
    const int arow = tid >> 1, acol = (tid & 1) << 2;
    const int brow = tid >> 5, bcol = (tid & 31) << 2;

    const bool aval = (bm + arow) < M;
    const float* Aptr = A + (size_t)(bm + arow)*K + acol;
    const float* Bptr = B + (size_t)brow*N + bn + bcol;

    float acc[8][8];
#pragma unroll
    for (int i = 0; i < 8; i++)
#pragma unroll
        for (int j = 0; j < 8; j++) acc[i][j] = 0.f;

    for (int k0 = 0; k0 < K; k0 += 8) {
        float4 af = aval ? *(const float4*)(Aptr + k0) : make_float4(0.f,0.f,0.f,0.f);
        float4 bf = *(const float4*)(Bptr + (size_t)k0*N);
        __syncthreads();
        As[acol+0][arow] = af.x; As[acol+1][arow] = af.y;
        As[acol+2][arow] = af.z; As[acol+3][arow] = af.w;
        *(float4*)&Bs[brow][bcol] = bf;
        __syncthreads();
#pragma unroll
        for (int k = 0; k < 8; k++) {
            float a[8], b[8];
#pragma unroll
            for (int i = 0; i < 8; i++) a[i] = As[k][ty*8+i];
#pragma unroll
            for (int j = 0; j < 8; j++) b[j] = Bs[k][tx*8+j];
#pragma unroll
            for (int i = 0; i < 8; i++)
#pragma unroll
                for (int j = 0; j < 8; j++) acc[i][j] = fmaf(a[i], b[j], acc[i][j]);
        }
    }
#pragma unroll
    for (int i = 0; i < 8; i++) {
        int r = bm + ty*8 + i;
        if (r >= M) break;
        float* crow = C + (size_t)r*N + bn + tx*8;
        if (Cadd) {
            const float* ar = Cadd + (size_t)r*N + bn + tx*8;
#pragma unroll
            for (int j = 0; j < 8; j++) crow[j] = acc[i][j] + ar[j];
        } else {
#pragma unroll
            for (int j = 0; j < 8; j++) crow[j] = acc[i][j];
        }
    }
}

// ---------------- RoPE (in place) ----------------
__global__ void rope_kernel(float* __restrict__ x, const int* __restrict__ pos, int nheads)
{
    int t = blockIdx.x, h = blockIdx.y, i = threadIdx.x;  // i < 64
    float* p = x + ((size_t)t*nheads + h)*HDn;
    float inv = powf(1.0e6f, -((float)i)/64.0f);
    float ang = (float)pos[t] * inv;
    float sv, cv; sincosf(ang, &sv, &cv);
    float a = p[i], b = p[i+64];
    p[i]    = a*cv - b*sv;
    p[i+64] = b*cv + a*sv;
}

// ---------------- causal GQA flash attention (fp32) ----------------
// grid (T/64, NH), 256 threads, BM=BN=64, HD=128
#define ATTN_SMEM_BYTES ((64*132*2 + 64*65 + 192) * 4)
__global__ void __launch_bounds__(256) attn_kernel(
    const float* __restrict__ q, const float* __restrict__ k,
    const float* __restrict__ v, float* __restrict__ out)
{
    extern __shared__ float sm[];
    float* Qs  = sm;              // 64 x 132
    float* KVs = sm + 64*132;     // 64 x 132
    float* Ps  = sm + 2*64*132;   // 64 x 65
    float* m_s = Ps + 64*65;
    float* l_s = m_s + 64;
    float* al_s = l_s + 64;

    const int tid = threadIdx.x;
    const int m0 = blockIdx.x * 64;
    const int h  = blockIdx.y;
    const int kvh = h / (NHn/NKVn);
    const float scale = 0.08838834764831845f;  // 128^-0.5

    {   // Q tile
        int r = tid >> 2, c = (tid & 3) * 32;
        const float* src = q + ((size_t)(m0 + r)*NHn + h)*HDn + c;
        float* dst = Qs + r*132 + c;
#pragma unroll
        for (int j = 0; j < 32; j += 4) *(float4*)(dst + j) = *(const float4*)(src + j);
    }
    if (tid < 64) { m_s[tid] = -INFINITY; l_s[tid] = 0.f; }

    const int tx = tid & 15, ty = tid >> 4;
    const int r0 = ty*4, sc0 = tx*4, oc0 = tx*8;
    float acc[4][8];
#pragma unroll
    for (int i = 0; i < 4; i++)
#pragma unroll
        for (int j = 0; j < 8; j++) acc[i][j] = 0.f;

    const int ntiles = m0/64 + 1;
    for (int t = 0; t < ntiles; ++t) {
        const int s0 = t*64;
        __syncthreads();
        {   // K tile
            int r = tid >> 2, c = (tid & 3)*32;
            const float* src = k + ((size_t)(s0 + r)*NKVn + kvh)*HDn + c;
            float* dst = KVs + r*132 + c;
#pragma unroll
            for (int j = 0; j < 32; j += 4) *(float4*)(dst + j) = *(const float4*)(src + j);
        }
        __syncthreads();
        // S = Q K^T (4x4 per thread)
        float s4[4][4];
#pragma unroll
        for (int i = 0; i < 4; i++)
#pragma unroll
            for (int j = 0; j < 4; j++) s4[i][j] = 0.f;
#pragma unroll 4
        for (int kk = 0; kk < HDn; kk += 4) {
            float4 a[4], b[4];
#pragma unroll
            for (int i = 0; i < 4; i++) a[i] = *(const float4*)(Qs + (r0+i)*132 + kk);
#pragma unroll
            for (int j = 0; j < 4; j++) b[j] = *(const float4*)(KVs + (sc0+j)*132 + kk);
#pragma unroll
            for (int i = 0; i < 4; i++)
#pragma unroll
                for (int j = 0; j < 4; j++)
                    s4[i][j] += a[i].x*b[j].x + a[i].y*b[j].y + a[i].z*b[j].z + a[i].w*b[j].w;
        }
#pragma unroll
        for (int i = 0; i < 4; i++)
#pragma unroll
            for (int j = 0; j < 4; j++) {
                float vv = s4[i][j]*scale;
                if (s0 + sc0 + j > m0 + r0 + i) vv = -1e30f;
                Ps[(r0+i)*65 + sc0 + j] = vv;
            }
        __syncthreads();
        {   // online softmax (4 threads per row)
            int r = tid >> 2, sub = tid & 3;
            float* prow = Ps + r*65 + sub*16;
            float mx = -INFINITY;
#pragma unroll
            for (int j2 = 0; j2 < 16; j2++) mx = fmaxf(mx, prow[j2]);
#pragma unroll
            for (int o = 1; o < 4; o <<= 1) mx = fmaxf(mx, __shfl_xor_sync(0xffffffffu, mx, o));
            float mprev = m_s[r];
            float mnew  = fmaxf(mprev, mx);
            float sum = 0.f;
#pragma unroll
            for (int j2 = 0; j2 < 16; j2++) { float p = __expf(prow[j2]-mnew); prow[j2] = p; sum += p; }
#pragma unroll
            for (int o = 1; o < 4; o <<= 1) sum += __shfl_xor_sync(0xffffffffu, sum, o);
            if (sub == 0) {
                float al = __expf(mprev - mnew);
                al_s[r] = al;
                l_s[r]  = l_s[r]*al + sum;
                m_s[r]  = mnew;
            }
        }
        __syncthreads();
        {   // V tile (reuse KVs)
            int r = tid >> 2, c = (tid & 3)*32;
            const float* src = v + ((size_t)(s0 + r)*NKVn + kvh)*HDn + c;
            float* dst = KVs + r*132 + c;
#pragma unroll
            for (int j = 0; j < 32; j += 4) *(float4*)(dst + j) = *(const float4*)(src + j);
        }
        __syncthreads();
        {   // O += P V  (4x8 per thread)
#pragma unroll
            for (int i = 0; i < 4; i++) {
                float al = al_s[r0+i];
#pragma unroll
                for (int j = 0; j < 8; j++) acc[i][j] *= al;
            }
#pragma unroll 4
            for (int s = 0; s < 64; s++) {
                float4 v0 = *(const float4*)(KVs + s*132 + oc0);
                float4 v1 = *(const float4*)(KVs + s*132 + oc0 + 4);
                float p[4];
#pragma unroll
                for (int i = 0; i < 4; i++) p[i] = Ps[(r0+i)*65 + s];
#pragma unroll
                for (int i = 0; i < 4; i++) {
                    acc[i][0] = fmaf(p[i], v0.x, acc[i][0]);
                    acc[i][1] = fmaf(p[i], v0.y, acc[i][1]);
                    acc[i][2] = fmaf(p[i], v0.z, acc[i][2]);
                    acc[i][3] = fmaf(p[i], v0.w, acc[i][3]);
                    acc[i][4] = fmaf(p[i], v1.x, acc[i][4]);
                    acc[i][5] = fmaf(p[i], v1.y, acc[i][5]);
                    acc[i][6] = fmaf(p[i], v1.z, acc[i][6]);
                    acc[i][7] = fmaf(p[i], v1.w, acc[i][7]);
                }
            }
        }
    }
    __syncthreads();
#pragma unroll
    for (int i = 0; i < 4; i++) {
        float inv = 1.f / l_s[r0+i];
        float* dst = out + ((size_t)(m0 + r0 + i)*NHn + h)*HDn + oc0;
#pragma unroll
        for (int j = 0; j < 8; j++) dst[j] = acc[i][j]*inv;
    }
}

// ---------------- router: softmax over 8 experts, top2, normalize ----------------
__global__ void __launch_bounds__(256) router_kernel(
    const float* __restrict__ x, const float* __restrict__ rw)
{
    int t = blockIdx.x;
    int w = threadIdx.x >> 5, lane = threadIdx.x & 31;
    __shared__ float lg[En];
    const float* xr = x + (size_t)t*Hn;
    float s = 0.f;
    for (int j = lane; j < Hn; j += 32) s += xr[j]*rw[(size_t)j*En + w];
#pragma unroll
    for (int o = 16; o > 0; o >>= 1) s += __shfl_xor_sync(0xffffffffu, s, o);
    if (lane == 0) lg[w] = s;
    __syncthreads();
    if (threadIdx.x == 0) {
        float mx = lg[0];
        for (int e = 1; e < En; e++) mx = fmaxf(mx, lg[e]);
        float p[En]; float sum = 0.f;
        for (int e = 0; e < En; e++) { p[e] = expf(lg[e]-mx); sum += p[e]; }
        for (int e = 0; e < En; e++) p[e] /= sum;
        int e0 = 0;
        for (int e = 1; e < En; e++) if (p[e] > p[e0]) e0 = e;
        int e1 = (e0 == 0) ? 1 : 0;
        for (int e = 0; e < En; e++) if (e != e0 && p[e] > p[e1]) e1 = e;
        float inv = 1.f/(p[e0]+p[e1]);
        g_te[t*2]   = e0; g_te[t*2+1] = e1;
        g_tw[t*2]   = p[e0]*inv; g_tw[t*2+1] = p[e1]*inv;
    }
}

__global__ void __launch_bounds__(128) sgate_kernel(
    const float* __restrict__ x, const float* __restrict__ wsg)
{
    int t = blockIdx.x, tid = threadIdx.x;
    __shared__ float red[128];
    const float* xr = x + (size_t)t*Hn;
    float s = 0.f;
    for (int j = tid; j < Hn; j += 128) s += xr[j]*wsg[j];
    red[tid] = s; __syncthreads();
    for (int o = 64; o > 0; o >>= 1) { if (tid < o) red[tid] += red[tid+o]; __syncthreads(); }
    if (tid == 0) g_sgate[t] = 1.f/(1.f + expf(-red[0]));
}

// ---------------- build per-expert permutation (single block) ----------------
__global__ void __launch_bounds__(256) build_perm_kernel()
{
    __shared__ int cnt_s[En], off_s[En], cur[En];
    int tid = threadIdx.x;
    if (tid < En) cnt_s[tid] = 0;
    __syncthreads();
    for (int t = tid; t < Tn; t += 256) {
        atomicAdd(&cnt_s[g_te[t*2]], 1);
        atomicAdd(&cnt_s[g_te[t*2+1]], 1);
    }
    __syncthreads();
    if (tid == 0) { int o = 0; for (int e = 0; e < En; e++) { off_s[e] = o; o += cnt_s[e]; } }
    __syncthreads();
    if (tid < En) cur[tid] = off_s[tid];
    __syncthreads();
    for (int t = tid; t < Tn; t += 256) {
        for (int s = 0; s < 2; s++) {
            int e = g_te[t*2+s];
            int p = atomicAdd(&cur[e], 1);
            g_ptok[p] = t; g_pslot[p] = s; g_pw[p] = g_tw[t*2+s];
        }
    }
    __syncthreads();
    if (tid < En) { g_cnt[tid] = cnt_s[tid]; g_off[tid] = off_s[tid]; }
}

// ---------------- grouped MoE GEMMs (row gather) ----------------
// Cbuf[p, 0:F] = x2[token(p)] @ W[e],  grid (F/128, 32, E)
__global__ void __launch_bounds__(256) gemm_moe_up(
    const float* __restrict__ X, const float* __restrict__ W, float* __restrict__ Cbuf)
{
    const int e = blockIdx.z;
    const int cnt = g_cnt[e], off = g_off[e];
    const int rt = blockIdx.y * 128;
    if (rt >= cnt) return;
    const int bn = blockIdx.x * 128;
    __shared__ float As[8][128];
    __shared__ float Bs[8][128];
    const int tid = threadIdx.x;
    const int tx = tid & 15, ty = tid >> 4;
    const int arow = tid >> 1, acol = (tid & 1) << 2;
    const int brow = tid >> 5, bcol = (tid & 31) << 2;

    int tok = (rt + arow < cnt) ? g_ptok[off + rt + arow] : -1;
    const float* Aptr = (tok >= 0) ? (X + (size_t)tok*Hn + acol) : nullptr;
    const float* Bptr = W + (size_t)e*Hn*Fn + (size_t)brow*Fn + bn + bcol;

    float acc[8][8];
#pragma unroll
    for (int i = 0; i < 8; i++)
#pragma unroll
        for (int j = 0; j < 8; j++) acc[i][j] = 0.f;

    for (int k0 = 0; k0 < Hn; k0 += 8) {
        float4 af = Aptr ? *(const float4*)(Aptr + k0) : make_float4(0.f,0.f,0.f,0.f);
        float4 bf = *(const float4*)(Bptr + (size_t)k0*Fn);
        __syncthreads();
        As[acol+0][arow] = af.x; As[acol+1][arow] = af.y;
        As[acol+2][arow] = af.z; As[acol+3][arow] = af.w;
        *(float4*)&Bs[brow][bcol] = bf;
        __syncthreads();
#pragma unroll
        for (int k = 0; k < 8; k++) {
            float a[8], b[8];
#pragma unroll
            for (int i = 0; i < 8; i++) a[i] = As[k][ty*8+i];
#pragma unroll
            for (int j = 0; j < 8; j++) b[j] = Bs[k][tx*8+j];
#pragma unroll
            for (int i = 0; i < 8; i++)
#pragma unroll
                for (int j = 0; j < 8; j++) acc[i][j] = fmaf(a[i], b[j], acc[i][j]);
        }
    }
#pragma unroll
    for (int i = 0; i < 8; i++) {
        int lr = rt + ty*8 + i;
        if (lr >= cnt) break;
        float* crow = Cbuf + (size_t)(off + lr)*Fn + bn + tx*8;
#pragma unroll
        for (int j = 0; j < 8; j++) crow[j] = acc[i][j];
    }
}

// g_moe[slot(p)][token(p)] = w(p) * (act[p] @ Wd[e]),  grid (H/128, 32, E)
__global__ void __launch_bounds__(256) gemm_moe_down(
    const float* __restrict__ ACT, const float* __restrict__ W)
{
    const int e = blockIdx.z;
    const int cnt = g_cnt[e], off = g_off[e];
    const int rt = blockIdx.y * 128;
    if (rt >= cnt) return;
    const int bn = blockIdx.x * 128;
    __shared__ float As[8][128];
    __shared__ float Bs[8][128];
    const int tid = threadIdx.x;
    const int tx = tid & 15, ty = tid >> 4;
    const int arow = tid >> 1, acol = (tid & 1) << 2;
    const int brow = tid >> 5, bcol = (tid & 31) << 2;

    const bool aval = (rt + arow) < cnt;
    const float* Aptr = ACT + (size_t)(off + rt + arow)*Fn + acol;
    const float* Bptr = W + (size_t)e*Fn*Hn + (size_t)brow*Hn + bn + bcol;

    float acc[8][8];
#pragma unroll
    for (int i = 0; i < 8; i++)
#pragma unroll
        for (int j = 0; j < 8; j++) acc[i][j] = 0.f;

    for (int k0 = 0; k0 < Fn; k0 += 8) {
        float4 af = aval ? *(const float4*)(Aptr + k0) : make_float4(0.f,0.f,0.f,0.f);
        float4 bf = *(const float4*)(Bptr + (size_t)k0*Hn);
        __syncthreads();
        As[acol+0][arow] = af.x; As[acol+1][arow] = af.y;
        As[acol+2][arow] = af.z; As[acol+3][arow] = af.w;
        *(float4*)&Bs[brow][bcol] = bf;
        __syncthreads();
#pragma unroll
        for (int k = 0; k < 8; k++) {
            float a[8], b[8];
#pragma unroll
            for (int i = 0; i < 8; i++) a[i] = As[k][ty*8+i];
#pragma unroll
            for (int j = 0; j < 8; j++) b[j] = Bs[k][tx*8+j];
#pragma unroll
            for (int i = 0; i < 8; i++)
#pragma unroll
                for (int j = 0; j < 8; j++) acc[i][j] = fmaf(a[i], b[j], acc[i][j]);
        }
    }
#pragma unroll
    for (int i = 0; i < 8; i++) {
        int lr = rt + ty*8 + i;
        if (lr >= cnt) break;
        int p = off + lr;
        int tok = g_ptok[p], slot = g_pslot[p];
        float wgt = g_pw[p];
        float* dst = g_moe + (size_t)slot*Tn*Hn + (size_t)tok*Hn + bn + tx*8;
#pragma unroll
        for (int j = 0; j < 8; j++) dst[j] = acc[i][j]*wgt;
    }
}

// ---------------- elementwise ----------------
__global__ void silumul_kernel(const float* __restrict__ g, const float* __restrict__ u,
                               float* __restrict__ y, int n4)
{
    int i = blockIdx.x*blockDim.x + threadIdx.x;
    for (; i < n4; i += gridDim.x*blockDim.x) {
        float4 gv = ((const float4*)g)[i];
        float4 uv = ((const float4*)u)[i];
        float4 r;
        r.x = gv.x/(1.f+__expf(-gv.x))*uv.x;
        r.y = gv.y/(1.f+__expf(-gv.y))*uv.y;
        r.z = gv.z/(1.f+__expf(-gv.z))*uv.z;
        r.w = gv.w/(1.f+__expf(-gv.w))*uv.w;
        ((float4*)y)[i] = r;
    }
}

__global__ void combine_kernel(const float* __restrict__ hidden, const float* __restrict__ so,
                               float* __restrict__ out)
{
    const int total = Tn*Hn;
    int i = blockIdx.x*blockDim.x + threadIdx.x;
    for (; i < total; i += gridDim.x*blockDim.x) {
        int t = i / Hn;
        out[i] = hidden[i] + g_moe[i] + g_moe[total + i] + g_sgate[t]*so[i];
    }
}

// ---------------- launch ----------------
extern "C" void kernel_launch(void* const* d_in, const int* in_sizes, int n_in,
                              void* d_out, int out_size)
{
    (void)in_sizes; (void)n_in; (void)out_size;
    const float* hs     = (const float*)d_in[0];
    const int*   pos    = (const int*)  d_in[1];
    const float* ln1    = (const float*)d_in[2];
    const float* ln2    = (const float*)d_in[3];
    const float* wq     = (const float*)d_in[4];
    const float* wk     = (const float*)d_in[5];
    const float* wv     = (const float*)d_in[6];
    const float* wo     = (const float*)d_in[7];
    const float* rw     = (const float*)d_in[8];
    const float* wg     = (const float*)d_in[9];
    const float* wu     = (const float*)d_in[10];
    const float* wd     = (const float*)d_in[11];
    const float* wsgt   = (const float*)d_in[12];
    const float* wsup   = (const float*)d_in[13];
    const float* wsdn   = (const float*)d_in[14];
    const float* wsg    = (const float*)d_in[15];
    float* out = (float*)d_out;

    float *x1p, *qp, *kp, *vp, *attnp, *hidp, *x2p, *gbufp, *ubufp, *sggp, *sgup, *sop;
    cudaGetSymbolAddress((void**)&x1p,   g_x1);
    cudaGetSymbolAddress((void**)&qp,    g_q);
    cudaGetSymbolAddress((void**)&kp,    g_k);
    cudaGetSymbolAddress((void**)&vp,    g_v);
    cudaGetSymbolAddress((void**)&attnp, g_attn);
    cudaGetSymbolAddress((void**)&hidp,  g_hidden);
    cudaGetSymbolAddress((void**)&x2p,   g_x2);
    cudaGetSymbolAddress((void**)&gbufp, g_gbuf);
    cudaGetSymbolAddress((void**)&ubufp, g_ubuf);
    cudaGetSymbolAddress((void**)&sggp,  g_sgg);
    cudaGetSymbolAddress((void**)&sgup,  g_sgu);
    cudaGetSymbolAddress((void**)&sop,   g_so);

    cudaFuncSetAttribute(attn_kernel, cudaFuncAttributeMaxDynamicSharedMemorySize, ATTN_SMEM_BYTES);

    // attention block
    rmsnorm_kernel<<<Tn, 256>>>(hs, ln1, x1p);
    gemm_f32<<<dim3(QD/128, Tn/128), 256>>>(x1p, wq, nullptr, qp, Tn, QD, Hn);
    gemm_f32<<<dim3(KD/128, Tn/128), 256>>>(x1p, wk, nullptr, kp, Tn, KD, Hn);
    gemm_f32<<<dim3(KD/128, Tn/128), 256>>>(x1p, wv, nullptr, vp, Tn, KD, Hn);
    rope_kernel<<<dim3(Tn, NHn),  64>>>(qp, pos, NHn);
    rope_kernel<<<dim3(Tn, NKVn), 64>>>(kp, pos, NKVn);
    attn_kernel<<<dim3(Tn/64, NHn), 256, ATTN_SMEM_BYTES>>>(qp, kp, vp, attnp);
    gemm_f32<<<dim3(Hn/128, Tn/128), 256>>>(attnp, wo, hs, hidp, Tn, Hn, QD);

    // MoE block
    rmsnorm_kernel<<<Tn, 256>>>(hidp, ln2, x2p);
    router_kernel<<<Tn, 256>>>(x2p, rw);
    sgate_kernel<<<Tn, 128>>>(x2p, wsg);
    build_perm_kernel<<<1, 256>>>();
    gemm_moe_up<<<dim3(Fn/128, 32, En), 256>>>(x2p, wg, gbufp);
    gemm_moe_up<<<dim3(Fn/128, 32, En), 256>>>(x2p, wu, ubufp);
    silumul_kernel<<<8192, 256>>>(gbufp, ubufp, gbufp, (2*Tn*Fn)/4);
    gemm_moe_down<<<dim3(Hn/128, 32, En), 256>>>(gbufp, wd);

    // shared expert
    gemm_f32<<<dim3(FSn/128, Tn/128), 256>>>(x2p, wsgt, nullptr, sggp, Tn, FSn, Hn);
    gemm_f32<<<dim3(FSn/128, Tn/128), 256>>>(x2p, wsup, nullptr, sgup, Tn, FSn, Hn);
    silumul_kernel<<<8192, 256>>>(sggp, sgup, sggp, (Tn*FSn)/4);
    gemm_f32<<<dim3(Hn/128, Tn/128), 256>>>(sggp, wsdn, nullptr, sop, Tn, Hn, FSn);

    combine_kernel<<<16384, 256>>>(hidp, sop, out);
}

// round 8
// speedup vs baseline: 1.0040x; 1.0040x over previous
#include <cuda_runtime.h>
#include <math.h>

#define Tn   2048
#define Hn   2048
#define NHn  16
#define NKVn 4
#define HDn  128
#define En   8
#define Fn   4096
#define FSn  4096
#define QD   (NHn*HDn)   // 2048
#define KD   (NKVn*HDn)  // 512

// ---------------- scratch (__device__ globals; no allocation allowed) ----------------
__device__ float g_x1[Tn*Hn];
__device__ float g_q[Tn*QD];
__device__ float g_k[Tn*KD];
__device__ float g_v[Tn*KD];
__device__ float g_attn[Tn*QD];
__device__ float g_hidden[Tn*Hn];
__device__ float g_x2[Tn*Hn];
__device__ float g_gbuf[2*Tn*Fn];   // gate proj / then act
__device__ float g_ubuf[2*Tn*Fn];   // up proj
__device__ float g_moe[2*Tn*Hn];    // per-slot expert outputs (scaled)
__device__ float g_sgg[Tn*FSn];     // shared-expert gate / act
__device__ float g_sgu[Tn*FSn];     // shared-expert up
__device__ float g_so[Tn*Hn];       // shared-expert out
__device__ float g_sgate[Tn];
__device__ int   g_te[Tn*2];
__device__ float g_tw[Tn*2];
__device__ int   g_ptok[2*Tn];
__device__ int   g_pslot[2*Tn];
__device__ float g_pw[2*Tn];
__device__ int   g_cnt[En];
__device__ int   g_off[En];

// ---------------- rmsnorm ----------------
__global__ void __launch_bounds__(256) rmsnorm_kernel(
    const float* __restrict__ x, const float* __restrict__ w, float* __restrict__ y)
{
    int t = blockIdx.x, tid = threadIdx.x;
    __shared__ float red[256];
    __shared__ float rs;
    const float* xr = x + (size_t)t*Hn;
    float s = 0.f;
    for (int j = tid; j < Hn; j += 256) { float v = xr[j]; s += v*v; }
    red[tid] = s; __syncthreads();
    for (int o = 128; o > 0; o >>= 1) { if (tid < o) red[tid] += red[tid+o]; __syncthreads(); }
    if (tid == 0) rs = rsqrtf(red[0]/(float)Hn + 1e-6f);
    __syncthreads();
    float* yr = y + (size_t)t*Hn;
    for (int j = tid; j < Hn; j += 256) yr[j] = xr[j]*rs*w[j];
}

// ---------------- generic fp32 GEMM: C = A@B (+Cadd), row-major ----------------
// 128x128 tile, BK=8, 256 threads, 8x8 per-thread register blocking.
// N multiple of 128, K multiple of 8; M guarded.
__global__ void __launch_bounds__(256) gemm_f32(
    const float* __restrict__ A, const float* __restrict__ B,
    const float* __restrict__ Cadd, float* __restrict__ C,
    int M, int N, int K)
{
    __shared__ float As[8][128];
    __shared__ float Bs[8][128];
    const int tid = threadIdx.x;
    const int bm = blockIdx.y * 128, bn = blockIdx.x * 128;
    const int tx = tid & 15, ty = tid >> 4;
    const int arow = tid >> 1, acol = (tid & 1) << 2;
    const int brow = tid >> 5, bcol = (tid & 31) << 2;

    const bool aval = (bm + arow) < M;
    const float* Aptr = A + (size_t)(bm + arow)*K + acol;
    const float* Bptr = B + (size_t)brow*N + bn + bcol;

    float acc[8][8];
#pragma unroll
    for (int i = 0; i < 8; i++)
#pragma unroll
        for (int j = 0; j < 8; j++) acc[i][j] = 0.f;

    for (int k0 = 0; k0 < K; k0 += 8) {
        float4 af = aval ? *(const float4*)(Aptr + k0) : make_float4(0.f,0.f,0.f,0.f);
        float4 bf = *(const float4*)(Bptr + (size_t)k0*N);
        __syncthreads();
        As[acol+0][arow] = af.x; As[acol+1][arow] = af.y;
        As[acol+2][arow] = af.z; As[acol+3][arow] = af.w;
        *(float4*)&Bs[brow][bcol] = bf;
        __syncthreads();
#pragma unroll
        for (int k = 0; k < 8; k++) {
            float a[8], b[8];
#pragma unroll
            for (int i = 0; i < 8; i++) a[i] = As[k][ty*8+i];
#pragma unroll
            for (int j = 0; j < 8; j++) b[j] = Bs[k][tx*8+j];
#pragma unroll
            for (int i = 0; i < 8; i++)
#pragma unroll
                for (int j = 0; j < 8; j++) acc[i][j] = fmaf(a[i], b[j], acc[i][j]);
        }
    }
#pragma unroll
    for (int i = 0; i < 8; i++) {
        int r = bm + ty*8 + i;
        if (r >= M) break;
        float* crow = C + (size_t)r*N + bn + tx*8;
        if (Cadd) {
            const float* ar = Cadd + (size_t)r*N + bn + tx*8;
#pragma unroll
            for (int j = 0; j < 8; j++) crow[j] = acc[i][j] + ar[j];
        } else {
#pragma unroll
            for (int j = 0; j < 8; j++) crow[j] = acc[i][j];
        }
    }
}

// ---------------- RoPE (in place) ----------------
__global__ void rope_kernel(float* __restrict__ x, const int* __restrict__ pos, int nheads)
{
    int t = blockIdx.x, h = blockIdx.y, i = threadIdx.x;  // i < 64
    float* p = x + ((size_t)t*nheads + h)*HDn;
    float inv = powf(1.0e6f, -((float)i)/64.0f);
    float ang = (float)pos[t] * inv;
    float sv, cv; sincosf(ang, &sv, &cv);
    float a = p[i], b = p[i+64];
    p[i]    = a*cv - b*sv;
    p[i+64] = b*cv + a*sv;
}

// ---------------- causal GQA flash attention (fp32) ----------------
// grid (T/64, NH), 256 threads, BM=BN=64, HD=128
#define ATTN_SMEM_BYTES ((64*132*2 + 64*65 + 192) * 4)
__global__ void __launch_bounds__(256) attn_kernel(
    const float* __restrict__ q, const float* __restrict__ k,
    const float* __restrict__ v, float* __restrict__ out)
{
    extern __shared__ float sm[];
    float* Qs  = sm;              // 64 x 132
    float* KVs = sm + 64*132;     // 64 x 132
    float* Ps  = sm + 2*64*132;   // 64 x 65
    float* m_s = Ps + 64*65;
    float* l_s = m_s + 64;
    float* al_s = l_s + 64;

    const int tid = threadIdx.x;
    const int m0 = blockIdx.x * 64;
    const int h  = blockIdx.y;
    const int kvh = h / (NHn/NKVn);
    const float scale = 0.08838834764831845f;  // 128^-0.5

    {   // Q tile
        int r = tid >> 2, c = (tid & 3) * 32;
        const float* src = q + ((size_t)(m0 + r)*NHn + h)*HDn + c;
        float* dst = Qs + r*132 + c;
#pragma unroll
        for (int j = 0; j < 32; j += 4) *(float4*)(dst + j) = *(const float4*)(src + j);
    }
    if (tid < 64) { m_s[tid] = -INFINITY; l_s[tid] = 0.f; }

    const int tx = tid & 15, ty = tid >> 4;
    const int r0 = ty*4, sc0 = tx*4, oc0 = tx*8;
    float acc[4][8];
#pragma unroll
    for (int i = 0; i < 4; i++)
#pragma unroll
        for (int j = 0; j < 8; j++) acc[i][j] = 0.f;

    const int ntiles = m0/64 + 1;
    for (int t = 0; t < ntiles; ++t) {
        const int s0 = t*64;
        __syncthreads();
        {   // K tile
            int r = tid >> 2, c = (tid & 3)*32;
            const float* src = k + ((size_t)(s0 + r)*NKVn + kvh)*HDn + c;
            float* dst = KVs + r*132 + c;
#pragma unroll
            for (int j = 0; j < 32; j += 4) *(float4*)(dst + j) = *(const float4*)(src + j);
        }
        __syncthreads();
        // S = Q K^T (4x4 per thread)
        float s4[4][4];
#pragma unroll
        for (int i = 0; i < 4; i++)
#pragma unroll
            for (int j = 0; j < 4; j++) s4[i][j] = 0.f;
#pragma unroll 4
        for (int kk = 0; kk < HDn; kk += 4) {
            float4 a[4], b[4];
#pragma unroll
            for (int i = 0; i < 4; i++) a[i] = *(const float4*)(Qs + (r0+i)*132 + kk);
#pragma unroll
            for (int j = 0; j < 4; j++) b[j] = *(const float4*)(KVs + (sc0+j)*132 + kk);
#pragma unroll
            for (int i = 0; i < 4; i++)
#pragma unroll
                for (int j = 0; j < 4; j++)
                    s4[i][j] += a[i].x*b[j].x + a[i].y*b[j].y + a[i].z*b[j].z + a[i].w*b[j].w;
        }
#pragma unroll
        for (int i = 0; i < 4; i++)
#pragma unroll
            for (int j = 0; j < 4; j++) {
                float vv = s4[i][j]*scale;
                if (s0 + sc0 + j > m0 + r0 + i) vv = -1e30f;
                Ps[(r0+i)*65 + sc0 + j] = vv;
            }
        __syncthreads();
        {   // online softmax (4 threads per row)
            int r = tid >> 2, sub = tid & 3;
            float* prow = Ps + r*65 + sub*16;
            float mx = -INFINITY;
#pragma unroll
            for (int j2 = 0; j2 < 16; j2++) mx = fmaxf(mx, prow[j2]);
#pragma unroll
            for (int o = 1; o < 4; o <<= 1) mx = fmaxf(mx, __shfl_xor_sync(0xffffffffu, mx, o));
            float mprev = m_s[r];
            float mnew  = fmaxf(mprev, mx);
            float sum = 0.f;
#pragma unroll
            for (int j2 = 0; j2 < 16; j2++) { float p = __expf(prow[j2]-mnew); prow[j2] = p; sum += p; }
#pragma unroll
            for (int o = 1; o < 4; o <<= 1) sum += __shfl_xor_sync(0xffffffffu, sum, o);
            if (sub == 0) {
                float al = __expf(mprev - mnew);
                al_s[r] = al;
                l_s[r]  = l_s[r]*al + sum;
                m_s[r]  = mnew;
            }
        }
        __syncthreads();
        {   // V tile (reuse KVs)
            int r = tid >> 2, c = (tid & 3)*32;
            const float* src = v + ((size_t)(s0 + r)*NKVn + kvh)*HDn + c;
            float* dst = KVs + r*132 + c;
#pragma unroll
            for (int j = 0; j < 32; j += 4) *(float4*)(dst + j) = *(const float4*)(src + j);
        }
        __syncthreads();
        {   // O += P V  (4x8 per thread)
#pragma unroll
            for (int i = 0; i < 4; i++) {
                float al = al_s[r0+i];
#pragma unroll
                for (int j = 0; j < 8; j++) acc[i][j] *= al;
            }
#pragma unroll 4
            for (int s = 0; s < 64; s++) {
                float4 v0 = *(const float4*)(KVs + s*132 + oc0);
                float4 v1 = *(const float4*)(KVs + s*132 + oc0 + 4);
                float p[4];
#pragma unroll
                for (int i = 0; i < 4; i++) p[i] = Ps[(r0+i)*65 + s];
#pragma unroll
                for (int i = 0; i < 4; i++) {
                    acc[i][0] = fmaf(p[i], v0.x, acc[i][0]);
                    acc[i][1] = fmaf(p[i], v0.y, acc[i][1]);
                    acc[i][2] = fmaf(p[i], v0.z, acc[i][2]);
                    acc[i][3] = fmaf(p[i], v0.w, acc[i][3]);
                    acc[i][4] = fmaf(p[i], v1.x, acc[i][4]);
                    acc[i][5] = fmaf(p[i], v1.y, acc[i][5]);
                    acc[i][6] = fmaf(p[i], v1.z, acc[i][6]);
                    acc[i][7] = fmaf(p[i], v1.w, acc[i][7]);
                }
            }
        }
    }
    __syncthreads();
#pragma unroll
    for (int i = 0; i < 4; i++) {
        float inv = 1.f / l_s[r0+i];
        float* dst = out + ((size_t)(m0 + r0 + i)*NHn + h)*HDn + oc0;
#pragma unroll
        for (int j = 0; j < 8; j++) dst[j] = acc[i][j]*inv;
    }
}

// ---------------- router: softmax over 8 experts, top2, normalize ----------------
__global__ void __launch_bounds__(256) router_kernel(
    const float* __restrict__ x, const float* __restrict__ rw)
{
    int t = blockIdx.x;
    int w = threadIdx.x >> 5, lane = threadIdx.x & 31;
    __shared__ float lg[En];
    const float* xr = x + (size_t)t*Hn;
    float s = 0.f;
    for (int j = lane; j < Hn; j += 32) s += xr[j]*rw[(size_t)j*En + w];
#pragma unroll
    for (int o = 16; o > 0; o >>= 1) s += __shfl_xor_sync(0xffffffffu, s, o);
    if (lane == 0) lg[w] = s;
    __syncthreads();
    if (threadIdx.x == 0) {
        float mx = lg[0];
        for (int e = 1; e < En; e++) mx = fmaxf(mx, lg[e]);
        float p[En]; float sum = 0.f;
        for (int e = 0; e < En; e++) { p[e] = expf(lg[e]-mx); sum += p[e]; }
        for (int e = 0; e < En; e++) p[e] /= sum;
        int e0 = 0;
        for (int e = 1; e < En; e++) if (p[e] > p[e0]) e0 = e;
        int e1 = (e0 == 0) ? 1 : 0;
        for (int e = 0; e < En; e++) if (e != e0 && p[e] > p[e1]) e1 = e;
        float inv = 1.f/(p[e0]+p[e1]);
        g_te[t*2]   = e0; g_te[t*2+1] = e1;
        g_tw[t*2]   = p[e0]*inv; g_tw[t*2+1] = p[e1]*inv;
    }
}

__global__ void __launch_bounds__(128) sgate_kernel(
    const float* __restrict__ x, const float* __restrict__ wsg)
{
    int t = blockIdx.x, tid = threadIdx.x;
    __shared__ float red[128];
    const float* xr = x + (size_t)t*Hn;
    float s = 0.f;
    for (int j = tid; j < Hn; j += 128) s += xr[j]*wsg[j];
    red[tid] = s; __syncthreads();
    for (int o = 64; o > 0; o >>= 1) { if (tid < o) red[tid] += red[tid+o]; __syncthreads(); }
    if (tid == 0) g_sgate[t] = 1.f/(1.f + expf(-red[0]));
}

// ---------------- build per-expert permutation (single block) ----------------
__global__ void __launch_bounds__(256) build_perm_kernel()
{
    __shared__ int cnt_s[En], off_s[En], cur[En];
    int tid = threadIdx.x;
    if (tid < En) cnt_s[tid] = 0;
    __syncthreads();
    for (int t = tid; t < Tn; t += 256) {
        atomicAdd(&cnt_s[g_te[t*2]], 1);
        atomicAdd(&cnt_s[g_te[t*2+1]], 1);
    }
    __syncthreads();
    if (tid == 0) { int o = 0; for (int e = 0; e < En; e++) { off_s[e] = o; o += cnt_s[e]; } }
    __syncthreads();
    if (tid < En) cur[tid] = off_s[tid];
    __syncthreads();
    for (int t = tid; t < Tn; t += 256) {
        for (int s = 0; s < 2; s++) {
            int e = g_te[t*2+s];
            int p = atomicAdd(&cur[e], 1);
            g_ptok[p] = t; g_pslot[p] = s; g_pw[p] = g_tw[t*2+s];
        }
    }
    __syncthreads();
    if (tid < En) { g_cnt[tid] = cnt_s[tid]; g_off[tid] = off_s[tid]; }
}

// ---------------- grouped MoE GEMMs (row gather) ----------------
// Cbuf[p, 0:F] = x2[token(p)] @ W[e],  grid (F/128, 32, E)
__global__ void __launch_bounds__(256) gemm_moe_up(
    const float* __restrict__ X, const float* __restrict__ W, float* __restrict__ Cbuf)
{
    const int e = blockIdx.z;
    const int cnt = g_cnt[e], off = g_off[e];
    const int rt = blockIdx.y * 128;
    if (rt >= cnt) return;
    const int bn = blockIdx.x * 128;
    __shared__ float As[8][128];
    __shared__ float Bs[8][128];
    const int tid = threadIdx.x;
    const int tx = tid & 15, ty = tid >> 4;
    const int arow = tid >> 1, acol = (tid & 1) << 2;
    const int brow = tid >> 5, bcol = (tid & 31) << 2;

    int tok = (rt + arow < cnt) ? g_ptok[off + rt + arow] : -1;
    const float* Aptr = (tok >= 0) ? (X + (size_t)tok*Hn + acol) : nullptr;
    const float* Bptr = W + (size_t)e*Hn*Fn + (size_t)brow*Fn + bn + bcol;

    float acc[8][8];
#pragma unroll
    for (int i = 0; i < 8; i++)
#pragma unroll
        for (int j = 0; j < 8; j++) acc[i][j] = 0.f;

    for (int k0 = 0; k0 < Hn; k0 += 8) {
        float4 af = Aptr ? *(const float4*)(Aptr + k0) : make_float4(0.f,0.f,0.f,0.f);
        float4 bf = *(const float4*)(Bptr + (size_t)k0*Fn);
        __syncthreads();
        As[acol+0][arow] = af.x; As[acol+1][arow] = af.y;
        As[acol+2][arow] = af.z; As[acol+3][arow] = af.w;
        *(float4*)&Bs[brow][bcol] = bf;
        __syncthreads();
#pragma unroll
        for (int k = 0; k < 8; k++) {
            float a[8], b[8];
#pragma unroll
            for (int i = 0; i < 8; i++) a[i] = As[k][ty*8+i];
#pragma unroll
            for (int j = 0; j < 8; j++) b[j] = Bs[k][tx*8+j];
#pragma unroll
            for (int i = 0; i < 8; i++)
#pragma unroll
                for (int j = 0; j < 8; j++) acc[i][j] = fmaf(a[i], b[j], acc[i][j]);
        }
    }
#pragma unroll
    for (int i = 0; i < 8; i++) {
        int lr = rt + ty*8 + i;
        if (lr >= cnt) break;
        float* crow = Cbuf + (size_t)(off + lr)*Fn + bn + tx*8;
#pragma unroll
        for (int j = 0; j < 8; j++) crow[j] = acc[i][j];
    }
}

// g_moe[slot(p)][token(p)] = w(p) * (act[p] @ Wd[e]),  grid (H/128, 32, E)
__global__ void __launch_bounds__(256) gemm_moe_down(
    const float* __restrict__ ACT, const float* __restrict__ W)
{
    const int e = blockIdx.z;
    const int cnt = g_cnt[e], off = g_off[e];
    const int rt = blockIdx.y * 128;
    if (rt >= cnt) return;
    const int bn = blockIdx.x * 128;
    __shared__ float As[8][128];
    __shared__ float Bs[8][128];
    const int tid = threadIdx.x;
    const int tx = tid & 15, ty = tid >> 4;
    const int arow = tid >> 1, acol = (tid & 1) << 2;
    const int brow = tid >> 5, bcol = (tid & 31) << 2;

    const bool aval = (rt + arow) < cnt;
    const float* Aptr = ACT + (size_t)(off + rt + arow)*Fn + acol;
    const float* Bptr = W + (size_t)e*Fn*Hn + (size_t)brow*Hn + bn + bcol;

    float acc[8][8];
#pragma unroll
    for (int i = 0; i < 8; i++)
#pragma unroll
        for (int j = 0; j < 8; j++) acc[i][j] = 0.f;

    for (int k0 = 0; k0 < Fn; k0 += 8) {
        float4 af = aval ? *(const float4*)(Aptr + k0) : make_float4(0.f,0.f,0.f,0.f);
        float4 bf = *(const float4*)(Bptr + (size_t)k0*Hn);
        __syncthreads();
        As[acol+0][arow] = af.x; As[acol+1][arow] = af.y;
        As[acol+2][arow] = af.z; As[acol+3][arow] = af.w;
        *(float4*)&Bs[brow][bcol] = bf;
        __syncthreads();
#pragma unroll
        for (int k = 0; k < 8; k++) {
            float a[8], b[8];
#pragma unroll
            for (int i = 0; i < 8; i++) a[i] = As[k][ty*8+i];
#pragma unroll
            for (int j = 0; j < 8; j++) b[j] = Bs[k][tx*8+j];
#pragma unroll
            for (int i = 0; i < 8; i++)
#pragma unroll
                for (int j = 0; j < 8; j++) acc[i][j] = fmaf(a[i], b[j], acc[i][j]);
        }
    }
#pragma unroll
    for (int i = 0; i < 8; i++) {
        int lr = rt + ty*8 + i;
        if (lr >= cnt) break;
        int p = off + lr;
        int tok = g_ptok[p], slot = g_pslot[p];
        float wgt = g_pw[p];
        float* dst = g_moe + (size_t)slot*Tn*Hn + (size_t)tok*Hn + bn + tx*8;
#pragma unroll
        for (int j = 0; j < 8; j++) dst[j] = acc[i][j]*wgt;
    }
}

// ---------------- elementwise ----------------
__global__ void silumul_kernel(const float* __restrict__ g, const float* __restrict__ u,
                               float* __restrict__ y, int n4)
{
    int i = blockIdx.x*blockDim.x + threadIdx.x;
    for (; i < n4; i += gridDim.x*blockDim.x) {
        float4 gv = ((const float4*)g)[i];
        float4 uv = ((const float4*)u)[i];
        float4 r;
        r.x = gv.x/(1.f+__expf(-gv.x))*uv.x;
        r.y = gv.y/(1.f+__expf(-gv.y))*uv.y;
        r.z = gv.z/(1.f+__expf(-gv.z))*uv.z;
        r.w = gv.w/(1.f+__expf(-gv.w))*uv.w;
        ((float4*)y)[i] = r;
    }
}

__global__ void combine_kernel(const float* __restrict__ hidden, const float* __restrict__ so,
                               float* __restrict__ out)
{
    const int total = Tn*Hn;
    int i = blockIdx.x*blockDim.x + threadIdx.x;
    for (; i < total; i += gridDim.x*blockDim.x) {
        int t = i / Hn;
        out[i] = hidden[i] + g_moe[i] + g_moe[total + i] + g_sgate[t]*so[i];
    }
}

// ---------------- launch ----------------
extern "C" void kernel_launch(void* const* d_in, const int* in_sizes, int n_in,
                              void* d_out, int out_size)
{
    (void)in_sizes; (void)n_in; (void)out_size;
    const float* hs     = (const float*)d_in[0];
    const int*   pos    = (const int*)  d_in[1];
    const float* ln1    = (const float*)d_in[2];
    const float* ln2    = (const float*)d_in[3];
    const float* wq     = (const float*)d_in[4];
    const float* wk     = (const float*)d_in[5];
    const float* wv     = (const float*)d_in[6];
    const float* wo     = (const float*)d_in[7];
    const float* rw     = (const float*)d_in[8];
    const float* wg     = (const float*)d_in[9];
    const float* wu     = (const float*)d_in[10];
    const float* wd     = (const float*)d_in[11];
    const float* wsgt   = (const float*)d_in[12];
    const float* wsup   = (const float*)d_in[13];
    const float* wsdn   = (const float*)d_in[14];
    const float* wsg    = (const float*)d_in[15];
    float* out = (float*)d_out;

    float *x1p, *qp, *kp, *vp, *attnp, *hidp, *x2p, *gbufp, *ubufp, *sggp, *sgup, *sop;
    cudaGetSymbolAddress((void**)&x1p,   g_x1);
    cudaGetSymbolAddress((void**)&qp,    g_q);
    cudaGetSymbolAddress((void**)&kp,    g_k);
    cudaGetSymbolAddress((void**)&vp,    g_v);
    cudaGetSymbolAddress((void**)&attnp, g_attn);
    cudaGetSymbolAddress((void**)&hidp,  g_hidden);
    cudaGetSymbolAddress((void**)&x2p,   g_x2);
    cudaGetSymbolAddress((void**)&gbufp, g_gbuf);
    cudaGetSymbolAddress((void**)&ubufp, g_ubuf);
    cudaGetSymbolAddress((void**)&sggp,  g_sgg);
    cudaGetSymbolAddress((void**)&sgup,  g_sgu);
    cudaGetSymbolAddress((void**)&sop,   g_so);

    cudaFuncSetAttribute(attn_kernel, cudaFuncAttributeMaxDynamicSharedMemorySize, ATTN_SMEM_BYTES);

    // attention block
    rmsnorm_kernel<<<Tn, 256>>>(hs, ln1, x1p);
    gemm_f32<<<dim3(QD/128, Tn/128), 256>>>(x1p, wq, nullptr, qp, Tn, QD, Hn);
    gemm_f32<<<dim3(KD/128, Tn/128), 256>>>(x1p, wk, nullptr, kp, Tn, KD, Hn);
    gemm_f32<<<dim3(KD/128, Tn/128), 256>>>(x1p, wv, nullptr, vp, Tn, KD, Hn);
    rope_kernel<<<dim3(Tn, NHn),  64>>>(qp, pos, NHn);
    rope_kernel<<<dim3(Tn, NKVn), 64>>>(kp, pos, NKVn);
    attn_kernel<<<dim3(Tn/64, NHn), 256, ATTN_SMEM_BYTES>>>(qp, kp, vp, attnp);
    gemm_f32<<<dim3(Hn/128, Tn/128), 256>>>(attnp, wo, hs, hidp, Tn, Hn, QD);

    // MoE block
    rmsnorm_kernel<<<Tn, 256>>>(hidp, ln2, x2p);
    router_kernel<<<Tn, 256>>>(x2p, rw);
    sgate_kernel<<<Tn, 128>>>(x2p, wsg);
    build_perm_kernel<<<1, 256>>>();
    gemm_moe_up<<<dim3(Fn/128, 32, En), 256>>>(x2p, wg, gbufp);
    gemm_moe_up<<<dim3(Fn/128, 32, En), 256>>>(x2p, wu, ubufp);
    silumul_kernel<<<8192, 256>>>(gbufp, ubufp, gbufp, (2*Tn*Fn)/4);
    gemm_moe_down<<<dim3(Hn/128, 32, En), 256>>>(gbufp, wd);

    // shared expert
    gemm_f32<<<dim3(FSn/128, Tn/128), 256>>>(x2p, wsgt, nullptr, sggp, Tn, FSn, Hn);
    gemm_f32<<<dim3(FSn/128, Tn/128), 256>>>(x2p, wsup, nullptr, sgup, Tn, FSn, Hn);
    silumul_kernel<<<8192, 256>>>(sggp, sgup, sggp, (Tn*FSn)/4);
    gemm_f32<<<dim3(Hn/128, Tn/128), 256>>>(sggp, wsdn, nullptr, sop, Tn, Hn, FSn);

    combine_kernel<<<16384, 256>>>(hidp, sop, out);
}